// round 10
// baseline (speedup 1.0000x reference)
#include <cuda_runtime.h>
#include <cuda_fp16.h>

#define NMAX   50000
#define EMAX   800000
#define INDIM  128
#define OUTDIM 64

// Scratch (device globals: allocation-free rule)
__device__ __half2 g_zh[NMAX * 32];              // z in fp16 (32 half2 / row)
__device__ float  g_s[NMAX];                     // src-half attention proj
__device__ float  g_t[NMAX];                     // dst-half attention proj
__device__ __align__(16) int g_meta[NMAX + 4];   // [0,N): cnt  [N]: allocator
__device__ int2   g_od[NMAX];                    // packed {offset, degree}
__device__ int    g_rank[EMAX];                  // per-edge rank in dst bucket
__device__ float2 g_edge[EMAX];                  // packed (src bits, ex)

#define G_CNT   (g_meta)
#define G_TOTAL (g_meta + NMAX)

// ---------------------------------------------------------------------------
__device__ __forceinline__ unsigned f2tf32(float f) {
    unsigned u;
    asm("cvt.rna.tf32.f32 %0, %1;" : "=r"(u) : "f"(f));
    return u;
}

__device__ __forceinline__ void mma_tf32(float c[4], const unsigned a[4],
                                         const unsigned b[2]) {
    asm("mma.sync.aligned.m16n8k8.row.col.f32.tf32.tf32.f32 "
        "{%0,%1,%2,%3}, {%4,%5,%6,%7}, {%8,%9}, {%0,%1,%2,%3};"
        : "+f"(c[0]), "+f"(c[1]), "+f"(c[2]), "+f"(c[3])
        : "r"(a[0]), "r"(a[1]), "r"(a[2]), "r"(a[3]), "r"(b[0]), "r"(b[1]));
}

// ---------------------------------------------------------------------------
// Kernel A (fused): blocks [0, NG): tensor-core tf32 GEMM z = h @ W
//   (64 rows/block, warp (w&3)=m-tile, (w>>2)=n-half; s/t projections folded).
//   blocks [NG, NG+HB): in-degree histogram + per-edge rank.
__global__ __launch_bounds__(256) void k_fused(const float* __restrict__ h,
                                               const float* __restrict__ W,
                                               const float* __restrict__ Wa,
                                               const int4* __restrict__ dst4,
                                               int N, int E4, int NG) {
    __shared__ unsigned sA[64 * 132];     // A tile as tf32 bits, conflict-free pad
    __shared__ float ps[2][64];           // s partials per n-half
    __shared__ float pt[2][64];           // t partials per n-half

    const int tid = threadIdx.x;

    if (blockIdx.x >= NG) {
        // ---- histogram + rank half ----
        int t = (blockIdx.x - NG) * 256 + tid;
        if (t < E4) {
            int4 d = __ldg(dst4 + t);
            int4 r;
            r.x = atomicAdd(&G_CNT[d.x], 1);
            r.y = atomicAdd(&G_CNT[d.y], 1);
            r.z = atomicAdd(&G_CNT[d.z], 1);
            r.w = atomicAdd(&G_CNT[d.w], 1);
            ((int4*)g_rank)[t] = r;
        }
        return;
    }

    // ---- GEMM half ----
    const int row0 = blockIdx.x * 64;
    const float4 f4z = make_float4(0.f, 0.f, 0.f, 0.f);

    // stage A tile (64 x 128 floats -> tf32 bits), guarded + zero-padded
    for (int idx = tid; idx < 64 * 32; idx += 256) {
        int r  = idx >> 5;
        int c4 = (idx & 31) * 4;
        int row = row0 + r;
        float4 v = (row < N) ? __ldg((const float4*)(h + (size_t)row * INDIM + c4))
                             : f4z;
        unsigned* dp = &sA[r * 132 + c4];
        dp[0] = f2tf32(v.x); dp[1] = f2tf32(v.y);
        dp[2] = f2tf32(v.z); dp[3] = f2tf32(v.w);
    }
    __syncthreads();

    const int w    = tid >> 5;
    const int lane = tid & 31;
    const int mt   = (w & 3) * 16;       // m-tile base row (within block)
    const int nh   = w >> 2;             // n-half
    const int n0   = nh * 32;
    const int g    = lane >> 2;          // group id (row within tile)
    const int t4   = lane & 3;           // thread in group (k / col-pair)

    float c[4][4];
#pragma unroll
    for (int nt = 0; nt < 4; nt++)
#pragma unroll
        for (int j = 0; j < 4; j++) c[nt][j] = 0.0f;

#pragma unroll
    for (int k0 = 0; k0 < INDIM; k0 += 8) {
        unsigned a[4];
        const unsigned* ap0 = &sA[(mt + g) * 132 + k0 + t4];
        const unsigned* ap1 = &sA[(mt + g + 8) * 132 + k0 + t4];
        a[0] = ap0[0];   // (row,   k)
        a[1] = ap1[0];   // (row+8, k)
        a[2] = ap0[4];   // (row,   k+4)
        a[3] = ap1[4];   // (row+8, k+4)
#pragma unroll
        for (int nt = 0; nt < 4; nt++) {
            int n = n0 + nt * 8 + g;
            unsigned b[2];
            b[0] = f2tf32(__ldg(W + (k0 + t4) * OUTDIM + n));
            b[1] = f2tf32(__ldg(W + (k0 + t4 + 4) * OUTDIM + n));
            mma_tf32(c[nt], a, b);
        }
    }

    // epilogue: z stores (fp16) + s/t projections
    float sp_lo = 0.f, sp_hi = 0.f, tp_lo = 0.f, tp_hi = 0.f;
    const int row_lo = row0 + mt + g;
    const int row_hi = row_lo + 8;
#pragma unroll
    for (int nt = 0; nt < 4; nt++) {
        int col = n0 + nt * 8 + t4 * 2;
        if (row_lo < N)
            g_zh[(size_t)row_lo * 32 + (col >> 1)] = __floats2half2_rn(c[nt][0], c[nt][1]);
        if (row_hi < N)
            g_zh[(size_t)row_hi * 32 + (col >> 1)] = __floats2half2_rn(c[nt][2], c[nt][3]);
        float wa0 = __ldg(Wa + col),          wa1 = __ldg(Wa + col + 1);
        float wb0 = __ldg(Wa + OUTDIM + col), wb1 = __ldg(Wa + OUTDIM + col + 1);
        sp_lo += c[nt][0] * wa0 + c[nt][1] * wa1;
        sp_hi += c[nt][2] * wa0 + c[nt][3] * wa1;
        tp_lo += c[nt][0] * wb0 + c[nt][1] * wb1;
        tp_hi += c[nt][2] * wb0 + c[nt][3] * wb1;
    }
#pragma unroll
    for (int o = 1; o <= 2; o <<= 1) {
        sp_lo += __shfl_xor_sync(0xffffffffu, sp_lo, o);
        sp_hi += __shfl_xor_sync(0xffffffffu, sp_hi, o);
        tp_lo += __shfl_xor_sync(0xffffffffu, tp_lo, o);
        tp_hi += __shfl_xor_sync(0xffffffffu, tp_hi, o);
    }
    if (t4 == 0) {
        ps[nh][mt + g]     = sp_lo;
        ps[nh][mt + g + 8] = sp_hi;
        pt[nh][mt + g]     = tp_lo;
        pt[nh][mt + g + 8] = tp_hi;
    }
    __syncthreads();
    if (tid < 64) {
        int row = row0 + tid;
        if (row < N) {
            g_s[row] = ps[0][tid] + ps[1][tid];
            g_t[row] = pt[0][tid] + pt[1][tid];
        }
    }
}

// ---------------------------------------------------------------------------
// K2: offsets via int4 + warp-shuffle scan; writes packed {offset, degree}.
__global__ __launch_bounds__(256) void k_alloc(int N) {
    __shared__ int wsum[8];
    __shared__ int cbase;
    const int tid = threadIdx.x;
    int base_i = blockIdx.x * 1024 + tid * 4;

    int4 v = make_int4(0, 0, 0, 0);
    if (base_i + 3 < N) {
        v = *(const int4*)(G_CNT + base_i);
    } else {
        if (base_i + 0 < N) v.x = G_CNT[base_i + 0];
        if (base_i + 1 < N) v.y = G_CNT[base_i + 1];
        if (base_i + 2 < N) v.z = G_CNT[base_i + 2];
    }
    int s = v.x + v.y + v.z + v.w;
    int lane = tid & 31, wid = tid >> 5;
    int inc = s;
#pragma unroll
    for (int o = 1; o < 32; o <<= 1) {
        int n = __shfl_up_sync(0xffffffffu, inc, o);
        if (lane >= o) inc += n;
    }
    if (lane == 31) wsum[wid] = inc;
    __syncthreads();
    if (tid == 0) {
        int run = 0;
#pragma unroll
        for (int k = 0; k < 8; k++) { int x = wsum[k]; wsum[k] = run; run += x; }
        cbase = atomicAdd(G_TOTAL, run);
    }
    __syncthreads();
    int o = cbase + wsum[wid] + inc - s;
    if (base_i + 0 < N) { g_od[base_i + 0] = make_int2(o, v.x); o += v.x; }
    if (base_i + 1 < N) { g_od[base_i + 1] = make_int2(o, v.y); o += v.y; }
    if (base_i + 2 < N) { g_od[base_i + 2] = make_int2(o, v.z); o += v.z; }
    if (base_i + 3 < N) { g_od[base_i + 3] = make_int2(o, v.w); }
}

// ---------------------------------------------------------------------------
// K3: bucket fill, atomic-free: pos = off[dst] + rank. Also restores g_meta
//     to zero for the next graph replay (alloc consumed the counts already).
__global__ __launch_bounds__(256) void k_fill(const int* __restrict__ src,
                                              const int* __restrict__ dst,
                                              int E) {
    int i = blockIdx.x * blockDim.x + threadIdx.x;
    int gthreads = gridDim.x * blockDim.x;
    for (int m = i; m <= NMAX; m += gthreads) g_meta[m] = 0;
    if (i >= E) return;
    int s = src[i];
    int d = dst[i];
    int r = g_rank[i];
    float ex = __expf(fmaxf(__ldg(g_s + s) + __ldg(g_t + d), 0.0f));
    int2 od = __ldg(g_od + d);
    g_edge[od.x + r] = make_float2(__int_as_float(s), ex);
}

// ---------------------------------------------------------------------------
// K4: one warp per dst node; half-warp split over fp16 z rows (128B = 1 line,
//     16 lanes x uint2). Convert to fp32, FMA, merge halves with xor-16,
//     single divide at the end.
__global__ __launch_bounds__(256) void k_node(float* __restrict__ out, int N) {
    int warp = (blockIdx.x * blockDim.x + threadIdx.x) >> 5;
    int lane = threadIdx.x & 31;
    if (warp >= N) return;

    int2 od  = __ldg(g_od + warp);
    int  beg = od.x;
    int  deg = od.y;

    const int q    = lane & 15;
    const int half = lane >> 4;

    const uint2* zr16 = (const uint2*)g_zh;   // 16 uint2 per z row
    float4 acc = make_float4(0.f, 0.f, 0.f, 0.f);
    float  den = 0.0f;

#pragma unroll 2
    for (int jb = 0; jb < deg; jb += 2) {
        int j = jb + half;
        if (j < deg) {
            float2 pr = __ldg(g_edge + beg + j);     // uniform per half-warp
            float  a  = pr.y;
            int    s2 = __float_as_int(pr.x);
            den += a;
            uint2 u = __ldg(zr16 + (size_t)s2 * 16 + q);
            float2 f0 = __half22float2(*(const __half2*)&u.x);
            float2 f1 = __half22float2(*(const __half2*)&u.y);
            acc.x += a * f0.x;
            acc.y += a * f0.y;
            acc.z += a * f1.x;
            acc.w += a * f1.y;
        }
    }

    den   += __shfl_xor_sync(0xffffffffu, den,   16);
    acc.x += __shfl_xor_sync(0xffffffffu, acc.x, 16);
    acc.y += __shfl_xor_sync(0xffffffffu, acc.y, 16);
    acc.z += __shfl_xor_sync(0xffffffffu, acc.z, 16);
    acc.w += __shfl_xor_sync(0xffffffffu, acc.w, 16);

    if (half == 0) {
        float rden = (deg > 0) ? (1.0f / den) : 0.0f;
        float4 o;
        o.x = fmaxf(acc.x * rden, 0.0f);
        o.y = fmaxf(acc.y * rden, 0.0f);
        o.z = fmaxf(acc.z * rden, 0.0f);
        o.w = fmaxf(acc.w * rden, 0.0f);
        *(float4*)(out + (size_t)warp * OUTDIM + q * 4) = o;
    }
}

// ---------------------------------------------------------------------------
extern "C" void kernel_launch(void* const* d_in, const int* in_sizes, int n_in,
                              void* d_out, int out_size) {
    const float* h   = (const float*)d_in[0];
    const float* W   = (const float*)d_in[1];
    const float* Wa  = (const float*)d_in[2];
    const int*   src = (const int*)d_in[3];
    const int*   dst = (const int*)d_in[4];
    float* out = (float*)d_out;

    int N  = in_sizes[0] / INDIM;
    int E  = in_sizes[3];
    int E4 = E >> 2;
    int NG = (N + 63) / 64;
    int HB = (E4 + 255) / 256;
    int NB = (N + 1023) >> 10;

    k_fused<<<NG + HB, 256>>>(h, W, Wa, (const int4*)dst, N, E4, NG);
    k_alloc<<<NB, 256>>>(N);
    k_fill <<<(E + 255) / 256, 256>>>(src, dst, E);
    k_node <<<(N * 32 + 255) / 256, 256>>>(out, N);
}

// round 11
// speedup vs baseline: 1.2042x; 1.2042x over previous
#include <cuda_runtime.h>
#include <cuda_fp16.h>

#define NMAX   50000
#define EMAX   800000
#define INDIM  128
#define OUTDIM 64

// Scratch (device globals: allocation-free rule)
__device__ __half2 g_zh[NMAX * 32];              // z in fp16 (32 half2 / row)
__device__ float  g_s[NMAX];                     // src-half attention proj
__device__ float  g_t[NMAX];                     // dst-half attention proj
__device__ __align__(16) int g_meta[NMAX + 4];   // [0,N): cnt  [N]: allocator
__device__ int2   g_od[NMAX];                    // packed {offset, degree}
__device__ __align__(16) int g_rank[EMAX];       // per-edge rank in dst bucket
__device__ float2 g_edge[EMAX];                  // packed (src bits, ex)

#define G_CNT   (g_meta)
#define G_TOTAL (g_meta + NMAX)

// ---------------------------------------------------------------------------
// f32x2 helpers (FFMA2 only reachable via PTX fma.rn.f32x2)
__device__ __forceinline__ unsigned long long splat2(float a) {
    unsigned long long r;
    asm("mov.b64 %0, {%1, %1};" : "=l"(r) : "f"(a));
    return r;
}
__device__ __forceinline__ void fma2(unsigned long long& d,
                                     unsigned long long a, unsigned long long b) {
    asm("fma.rn.f32x2 %0, %1, %2, %0;" : "+l"(d) : "l"(a), "l"(b));
}

// ---------------------------------------------------------------------------
// Kernel A (fused): blocks [0, NG) compute z = h @ W (FFMA2, fp16 z store,
//                   s/t folded); blocks [NG, NG+HB) do histogram + rank.
__global__ __launch_bounds__(256) void k_fused(const float* __restrict__ h,
                                               const float* __restrict__ W,
                                               const float* __restrict__ Wa,
                                               const int4* __restrict__ dst4,
                                               int N, int E4, int NG) {
    __shared__ float2 sw2[INDIM * 32];

    if (blockIdx.x >= NG) {
        int t = (blockIdx.x - NG) * 256 + threadIdx.x;
        if (t < E4) {
            int4 d = __ldg(dst4 + t);
            int4 r;
            r.x = atomicAdd(&G_CNT[d.x], 1);
            r.y = atomicAdd(&G_CNT[d.y], 1);
            r.z = atomicAdd(&G_CNT[d.z], 1);
            r.w = atomicAdd(&G_CNT[d.w], 1);
            ((int4*)g_rank)[t] = r;
        }
        return;
    }

    // ---- GEMM half ----
    const int tid  = threadIdx.x;
    const int row0 = blockIdx.x * 64;

    const float2* W2 = (const float2*)W;
    for (int idx = tid; idx < INDIM * 32; idx += 256)
        sw2[idx] = W2[idx];
    __syncthreads();

    const int tx = tid & 15;
    const int ty = tid >> 4;

    int  rows[4];
    bool rv[4];
#pragma unroll
    for (int i = 0; i < 4; i++) { rows[i] = row0 + ty + 16 * i; rv[i] = rows[i] < N; }

    unsigned long long acc2[4][2];
#pragma unroll
    for (int i = 0; i < 4; i++) { acc2[i][0] = 0ull; acc2[i][1] = 0ull; }

    const float4 f4z = make_float4(0.f, 0.f, 0.f, 0.f);

#pragma unroll 4
    for (int k = 0; k < INDIM; k += 4) {
        float4 hv[4];
#pragma unroll
        for (int i = 0; i < 4; i++)
            hv[i] = rv[i] ? __ldg((const float4*)(h + (size_t)rows[i] * INDIM + k)) : f4z;
#pragma unroll
        for (int ks = 0; ks < 4; ks++) {
            unsigned long long w0 = *(const unsigned long long*)&sw2[(k + ks) * 32 + tx];
            unsigned long long w1 = *(const unsigned long long*)&sw2[(k + ks) * 32 + tx + 16];
#pragma unroll
            for (int i = 0; i < 4; i++) {
                const float* hp = &hv[i].x;
                unsigned long long aa = splat2(hp[ks]);
                fma2(acc2[i][0], aa, w0);
                fma2(acc2[i][1], aa, w1);
            }
        }
    }

    float wa_s[2][2], wa_t[2][2];
#pragma unroll
    for (int j = 0; j < 2; j++) {
        int c = (tx + 16 * j) * 2;
        wa_s[j][0] = __ldg(Wa + c);          wa_s[j][1] = __ldg(Wa + c + 1);
        wa_t[j][0] = __ldg(Wa + OUTDIM + c); wa_t[j][1] = __ldg(Wa + OUTDIM + c + 1);
    }

#pragma unroll
    for (int i = 0; i < 4; i++) {
        float2 a0 = *(float2*)&acc2[i][0];
        float2 a1 = *(float2*)&acc2[i][1];
        if (rv[i]) {
            __half2* zr = g_zh + (size_t)rows[i] * 32;
            zr[tx]      = __floats2half2_rn(a0.x, a0.y);
            zr[tx + 16] = __floats2half2_rn(a1.x, a1.y);
        }
        float sp = a0.x * wa_s[0][0] + a0.y * wa_s[0][1]
                 + a1.x * wa_s[1][0] + a1.y * wa_s[1][1];
        float tp = a0.x * wa_t[0][0] + a0.y * wa_t[0][1]
                 + a1.x * wa_t[1][0] + a1.y * wa_t[1][1];
#pragma unroll
        for (int off = 8; off > 0; off >>= 1) {
            sp += __shfl_xor_sync(0xffffffffu, sp, off, 16);
            tp += __shfl_xor_sync(0xffffffffu, tp, off, 16);
        }
        if (tx == 0 && rv[i]) { g_s[rows[i]] = sp; g_t[rows[i]] = tp; }
    }
}

// ---------------------------------------------------------------------------
// K2: offsets via int4 + warp-shuffle scan; writes packed {offset, degree}.
__global__ __launch_bounds__(256) void k_alloc(int N) {
    __shared__ int wsum[8];
    __shared__ int cbase;
    const int tid = threadIdx.x;
    int base_i = blockIdx.x * 1024 + tid * 4;

    int4 v = make_int4(0, 0, 0, 0);
    if (base_i + 3 < N) {
        v = *(const int4*)(G_CNT + base_i);
    } else {
        if (base_i + 0 < N) v.x = G_CNT[base_i + 0];
        if (base_i + 1 < N) v.y = G_CNT[base_i + 1];
        if (base_i + 2 < N) v.z = G_CNT[base_i + 2];
    }
    int s = v.x + v.y + v.z + v.w;
    int lane = tid & 31, wid = tid >> 5;
    int inc = s;
#pragma unroll
    for (int o = 1; o < 32; o <<= 1) {
        int n = __shfl_up_sync(0xffffffffu, inc, o);
        if (lane >= o) inc += n;
    }
    if (lane == 31) wsum[wid] = inc;
    __syncthreads();
    if (tid == 0) {
        int run = 0;
#pragma unroll
        for (int k = 0; k < 8; k++) { int x = wsum[k]; wsum[k] = run; run += x; }
        cbase = atomicAdd(G_TOTAL, run);
    }
    __syncthreads();
    int o = cbase + wsum[wid] + inc - s;
    if (base_i + 0 < N) { g_od[base_i + 0] = make_int2(o, v.x); o += v.x; }
    if (base_i + 1 < N) { g_od[base_i + 1] = make_int2(o, v.y); o += v.y; }
    if (base_i + 2 < N) { g_od[base_i + 2] = make_int2(o, v.z); o += v.z; }
    if (base_i + 3 < N) { g_od[base_i + 3] = make_int2(o, v.w); }
}

// ---------------------------------------------------------------------------
// K3: bucket fill, atomic-free, 4 edges/thread (int4 loads, ~12 independent
//     gathers in flight, no dependent chains). Also restores g_meta to zero
//     for the next graph replay.
__global__ __launch_bounds__(256) void k_fill(const int4* __restrict__ src4,
                                              const int4* __restrict__ dst4,
                                              int E4) {
    int t = blockIdx.x * blockDim.x + threadIdx.x;
    int gthreads = gridDim.x * blockDim.x;
    for (int m = t; m <= NMAX; m += gthreads) g_meta[m] = 0;
    if (t >= E4) return;

    int4 s4 = __ldg(src4 + t);
    int4 d4 = __ldg(dst4 + t);
    int4 r4 = __ldg(((const int4*)g_rank) + t);
    int si[4] = {s4.x, s4.y, s4.z, s4.w};
    int di[4] = {d4.x, d4.y, d4.z, d4.w};
    int ri[4] = {r4.x, r4.y, r4.z, r4.w};

    float sv[4], tv[4];
    int   ofs[4];
#pragma unroll
    for (int k = 0; k < 4; k++) sv[k] = __ldg(g_s + si[k]);
#pragma unroll
    for (int k = 0; k < 4; k++) tv[k] = __ldg(g_t + di[k]);
#pragma unroll
    for (int k = 0; k < 4; k++) ofs[k] = __ldg(&g_od[di[k]].x);

#pragma unroll
    for (int k = 0; k < 4; k++) {
        float ex = __expf(fmaxf(sv[k] + tv[k], 0.0f));
        g_edge[ofs[k] + ri[k]] = make_float2(__int_as_float(si[k]), ex);
    }
}

// ---------------------------------------------------------------------------
// K4: one warp per dst node; half-warp split over fp16 z rows (128B = 1 line,
//     16 lanes x uint2). Unroll 4 -> up to 4 independent gathers in flight.
__global__ __launch_bounds__(256) void k_node(float* __restrict__ out, int N) {
    int warp = (blockIdx.x * blockDim.x + threadIdx.x) >> 5;
    int lane = threadIdx.x & 31;
    if (warp >= N) return;

    int2 od  = __ldg(g_od + warp);
    int  beg = od.x;
    int  deg = od.y;

    const int q    = lane & 15;
    const int half = lane >> 4;

    const uint2* zr16 = (const uint2*)g_zh;   // 16 uint2 per z row
    float4 acc = make_float4(0.f, 0.f, 0.f, 0.f);
    float  den = 0.0f;

#pragma unroll 4
    for (int jb = 0; jb < deg; jb += 2) {
        int j = jb + half;
        if (j < deg) {
            float2 pr = __ldg(g_edge + beg + j);     // uniform per half-warp
            float  a  = pr.y;
            int    s2 = __float_as_int(pr.x);
            den += a;
            uint2 u = __ldg(zr16 + (size_t)s2 * 16 + q);
            float2 f0 = __half22float2(*(const __half2*)&u.x);
            float2 f1 = __half22float2(*(const __half2*)&u.y);
            acc.x += a * f0.x;
            acc.y += a * f0.y;
            acc.z += a * f1.x;
            acc.w += a * f1.y;
        }
    }

    den   += __shfl_xor_sync(0xffffffffu, den,   16);
    acc.x += __shfl_xor_sync(0xffffffffu, acc.x, 16);
    acc.y += __shfl_xor_sync(0xffffffffu, acc.y, 16);
    acc.z += __shfl_xor_sync(0xffffffffu, acc.z, 16);
    acc.w += __shfl_xor_sync(0xffffffffu, acc.w, 16);

    if (half == 0) {
        float rden = (deg > 0) ? (1.0f / den) : 0.0f;
        float4 o;
        o.x = fmaxf(acc.x * rden, 0.0f);
        o.y = fmaxf(acc.y * rden, 0.0f);
        o.z = fmaxf(acc.z * rden, 0.0f);
        o.w = fmaxf(acc.w * rden, 0.0f);
        *(float4*)(out + (size_t)warp * OUTDIM + q * 4) = o;
    }
}

// ---------------------------------------------------------------------------
extern "C" void kernel_launch(void* const* d_in, const int* in_sizes, int n_in,
                              void* d_out, int out_size) {
    const float* h   = (const float*)d_in[0];
    const float* W   = (const float*)d_in[1];
    const float* Wa  = (const float*)d_in[2];
    const int*   src = (const int*)d_in[3];
    const int*   dst = (const int*)d_in[4];
    float* out = (float*)d_out;

    int N  = in_sizes[0] / INDIM;
    int E  = in_sizes[3];
    int E4 = E >> 2;
    int NG = (N + 63) / 64;
    int HB = (E4 + 255) / 256;
    int NB = (N + 1023) >> 10;

    k_fused<<<NG + HB, 256>>>(h, W, Wa, (const int4*)dst, N, E4, NG);
    k_alloc<<<NB, 256>>>(N);
    k_fill <<<(E4 + 255) / 256, 256>>>((const int4*)src, (const int4*)dst, E4);
    k_node <<<(N * 32 + 255) / 256, 256>>>(out, N);
}